// round 5
// baseline (speedup 1.0000x reference)
#include <cuda_runtime.h>
#include <cstdint>

#define NN 4
#define C  64
#define H  160
#define W  320
#define DISP 48
#define G  8
#define HW (H*W)
#define ROWB 64                        // 16 floats per w position
#define TILE_BYTES (W * 16 * 4)        // 20KB per buffer
#define NTILES (H * NN * 4)            // 2560 tiles (h, n, group-pair)
#define NCTA 444                       // 148 SMs * 3 CTAs

// XOR swizzle, 16B granularity. Compute lanes step w by 2 -> (w>>1) steps 1
// per lane -> 8-lane LDS.128 phases hit 8 distinct 16B chunks: conflict-free.
__device__ __forceinline__ unsigned sw_off(int w, int colbyte) {
    unsigned off = (unsigned)(w * ROWB + colbyte);
    off ^= (((unsigned)w >> 1) & 7u) << 4;
    return off;
}

__device__ __forceinline__ void cp_async4(uint32_t dst, const float* src) {
    asm volatile("cp.async.ca.shared.global [%0], [%1], 4;\n"
                 :: "r"(dst), "l"(src));
}
#define CP_COMMIT() asm volatile("cp.async.commit_group;\n" ::: "memory")
#define CP_WAIT0()  asm volatile("cp.async.wait_group 0;\n" ::: "memory")

#define DOT(lw, s) (lw[0]*ra[s].x + lw[1]*ra[s].y + lw[2]*ra[s].z + lw[3]*ra[s].w + \
                    lw[4]*rb[s].x + lw[5]*rb[s].y + lw[6]*rb[s].z + lw[7]*rb[s].w)

__global__ __launch_bounds__(320, 3)
void gwc_kernel(const float* __restrict__ lg,
                const float* __restrict__ rg,
                float* __restrict__ out) {
    __shared__ __align__(16) char rS[2][TILE_BYTES];

    const int tid = threadIdx.x;
    const int gl  = tid / 160;           // local group 0/1 within pair
    const int w0  = (tid % 160) * 2;     // this thread's 2 output columns
    const int cb  = gl * 32;             // byte offset of group's 8 channels

    const uint32_t sbase0 = (uint32_t)__cvta_generic_to_shared(rS[0]);
    const uint32_t sbase1 = (uint32_t)__cvta_generic_to_shared(rS[1]);

    // ---- Prologue: stage first tile into buffer 0 ----
    int t = blockIdx.x;
    if (t < NTILES) {
        int h  = t % H;
        int nq = t / H;
        int n  = nq % NN;
        int gp = nq / NN;
        const float* rbase = rg + ((n * C + gp * 16) * H + h) * W + tid;
        #pragma unroll
        for (int c = 0; c < 16; ++c)
            cp_async4(sbase0 + sw_off(tid, c * 4), rbase + c * HW);
        CP_COMMIT();
        CP_WAIT0();
    }
    __syncthreads();

    int p = 0;
    for (; t < NTILES; t += NCTA) {
        const int h  = t % H;
        const int nq = t / H;
        const int n  = nq % NN;
        const int gp = nq / NN;
        const int g  = gp * 2 + gl;
        const uint32_t buf  = p ? sbase1 : sbase0;
        const uint32_t nbuf = p ? sbase0 : sbase1;

        // ---- Prefetch next tile into the spare buffer (no reg cost) ----
        const int tn = t + NCTA;
        if (tn < NTILES) {
            int hn  = tn % H;
            int nqn = tn / H;
            int nn2 = nqn % NN;
            int gpn = nqn / NN;
            const float* rb2 = rg + ((nn2 * C + gpn * 16) * H + hn) * W + tid;
            #pragma unroll
            for (int c = 0; c < 16; ++c)
                cp_async4(nbuf + sw_off(tid, c * 4), rb2 + c * HW);
        }
        CP_COMMIT();

        // ---- l channels for this tile: 8 coalesced LDG.64 ----
        const float* lp = lg + ((n * C + g * 8) * H + h) * W + w0;
        float lwA[8], lwB[8];
        #pragma unroll
        for (int c = 0; c < 8; ++c) {
            float2 v = *(const float2*)(lp + c * HW);
            lwA[c] = v.x; lwB[c] = v.y;
        }

        // ---- Compute: 2-slot sliding window over disparity ----
        float4 ra[2], rb[2];
        ra[0] = *(const float4*)__cvta_shared_to_generic(buf + sw_off(w0, cb));
        rb[0] = *(const float4*)__cvta_shared_to_generic(buf + sw_off(w0, cb + 16));
        ra[1] = *(const float4*)__cvta_shared_to_generic(buf + sw_off(w0 + 1, cb));
        rb[1] = *(const float4*)__cvta_shared_to_generic(buf + sw_off(w0 + 1, cb + 16));

        float* op = out + (((n * G + g) * DISP) * H + h) * W + w0;

        if (w0 >= DISP) {
            #pragma unroll 4
            for (int d2 = 0; d2 < DISP; d2 += 2) {
                #pragma unroll
                for (int e = 0; e < 2; ++e) {
                    const int d = d2 + e;
                    if (d > 0) {
                        const int wn = w0 - d;
                        ra[e] = *(const float4*)__cvta_shared_to_generic(buf + sw_off(wn, cb));
                        rb[e] = *(const float4*)__cvta_shared_to_generic(buf + sw_off(wn, cb + 16));
                    }
                    float2 o;
                    o.x = DOT(lwA, e) * 0.125f;
                    o.y = DOT(lwB, 1 - e) * 0.125f;
                    __stcs((float2*)(op + d * HW), o);
                }
            }
        } else {
            #pragma unroll 4
            for (int d2 = 0; d2 < DISP; d2 += 2) {
                #pragma unroll
                for (int e = 0; e < 2; ++e) {
                    const int d  = d2 + e;
                    const int wn = w0 - d;
                    if (d > 0 && wn >= 0) {
                        ra[e] = *(const float4*)__cvta_shared_to_generic(buf + sw_off(wn, cb));
                        rb[e] = *(const float4*)__cvta_shared_to_generic(buf + sw_off(wn, cb + 16));
                    }
                    float2 o;
                    o.x = (w0     >= d) ? DOT(lwA, e) * 0.125f     : 1.0f;
                    o.y = (w0 + 1 >= d) ? DOT(lwB, 1 - e) * 0.125f : 1.0f;
                    __stcs((float2*)(op + d * HW), o);
                }
            }
        }

        CP_WAIT0();          // next tile's data landed
        __syncthreads();     // all warps done with buf before it's reused
        p ^= 1;
    }
}

extern "C" void kernel_launch(void* const* d_in, const int* in_sizes, int n_in,
                              void* d_out, int out_size) {
    const float* l = (const float*)d_in[0];
    const float* r = (const float*)d_in[1];
    float* out = (float*)d_out;

    gwc_kernel<<<NCTA, 320>>>(l, r, out);
}

// round 6
// speedup vs baseline: 1.2733x; 1.2733x over previous
#include <cuda_runtime.h>

#define NN 4
#define C  64
#define H  160
#define W  320
#define DISP 48
#define G  8
#define HW (H*W)
#define ROWB 32                        // 8 floats per w position (one group)
#define SMEM_BYTES (W * ROWB)          // 10KB

// XOR swizzle, 16B granularity, for 32B rows.
// Compute lanes step w by 2 (addr step 64B): banks per 8-lane phase =
// {0,20,8,28,16,4,24,12}(+0..3) -> all 32 banks, conflict-free LDS.128.
// Bijective: bits[4:7) ^= bits[6:9).
__device__ __forceinline__ unsigned sw_off(int w, int colbyte) {
    unsigned off = (unsigned)(w * ROWB + colbyte);
    off ^= (((unsigned)w >> 1) & 7u) << 4;
    return off;
}

// Two independent 4-FFMA chains + add: dep depth ~20 cyc instead of 32.
#define DOT(lw, s)                                                      \
    ((lw[0]*ra[s].x + lw[1]*ra[s].y + lw[2]*ra[s].z + lw[3]*ra[s].w) +  \
     (lw[4]*rb[s].x + lw[5]*rb[s].y + lw[6]*rb[s].z + lw[7]*rb[s].w))

__global__ __launch_bounds__(160, 7)
void gwc_kernel(const float* __restrict__ lg,
                const float* __restrict__ rg,
                float* __restrict__ out) {
    __shared__ __align__(16) char rS[SMEM_BYTES];

    const int h   = blockIdx.x;
    const int n   = blockIdx.y;
    const int g   = blockIdx.z;
    const int tid = threadIdx.x;
    const int w0  = tid * 2;             // this thread's 2 output columns

    // ---- l loads first: 8 coalesced LDG.64, latency hides behind staging ----
    const float* lp = lg + ((n * C + g * 8) * H + h) * W + w0;
    float lwA[8], lwB[8];
    #pragma unroll
    for (int c = 0; c < 8; ++c) {
        float2 v = *(const float2*)(lp + c * HW);
        lwA[c] = v.x; lwB[c] = v.y;
    }

    // ---- Stage this group's 8 r channels, transposed [w][c], swizzled ----
    // 640 float4 stores: 4 per thread. Load all globals first (MLP), then STS.
    {
        const float* rbase = rg + ((n * C + g * 8) * H + h) * W;
        float4 rv[4];
        int ws[4];
        #pragma unroll
        for (int k = 0; k < 4; ++k) {
            int i  = tid + k * 160;
            int w  = i % W;
            int c4 = (i / W) * 4;        // 0 or 4
            int gb = c4 * HW + w;
            ws[k] = (int)sw_off(w, c4 * 4);
            rv[k].x = rbase[gb];
            rv[k].y = rbase[gb + HW];
            rv[k].z = rbase[gb + 2 * HW];
            rv[k].w = rbase[gb + 3 * HW];
        }
        #pragma unroll
        for (int k = 0; k < 4; ++k)
            *(float4*)(rS + ws[k]) = rv[k];
    }
    __syncthreads();

    // ---- Compute: 2-slot sliding window over disparity ----
    float4 ra[2], rb[2];                 // slot p = parity of r position
    ra[0] = *(const float4*)(rS + sw_off(w0, 0));
    rb[0] = *(const float4*)(rS + sw_off(w0, 16));
    ra[1] = *(const float4*)(rS + sw_off(w0 + 1, 0));
    rb[1] = *(const float4*)(rS + sw_off(w0 + 1, 16));

    float* op = out + (((n * G + g) * DISP) * H + h) * W + w0;

    if (w0 >= DISP) {
        #pragma unroll 4
        for (int d2 = 0; d2 < DISP; d2 += 2) {
            #pragma unroll
            for (int e = 0; e < 2; ++e) {
                const int d = d2 + e;
                if (d > 0) {             // new position w0-d has parity e
                    const int wn = w0 - d;
                    ra[e] = *(const float4*)(rS + sw_off(wn, 0));
                    rb[e] = *(const float4*)(rS + sw_off(wn, 16));
                }
                float2 o;
                o.x = DOT(lwA, e) * 0.125f;       // pos w0-d
                o.y = DOT(lwB, 1 - e) * 0.125f;   // pos w0+1-d
                __stcs((float2*)(op + d * HW), o);
            }
        }
    } else {
        #pragma unroll 4
        for (int d2 = 0; d2 < DISP; d2 += 2) {
            #pragma unroll
            for (int e = 0; e < 2; ++e) {
                const int d  = d2 + e;
                const int wn = w0 - d;
                if (d > 0 && wn >= 0) {
                    ra[e] = *(const float4*)(rS + sw_off(wn, 0));
                    rb[e] = *(const float4*)(rS + sw_off(wn, 16));
                }
                float2 o;
                o.x = (w0     >= d) ? DOT(lwA, e) * 0.125f     : 1.0f;
                o.y = (w0 + 1 >= d) ? DOT(lwB, 1 - e) * 0.125f : 1.0f;
                __stcs((float2*)(op + d * HW), o);
            }
        }
    }
}

extern "C" void kernel_launch(void* const* d_in, const int* in_sizes, int n_in,
                              void* d_out, int out_size) {
    const float* l = (const float*)d_in[0];
    const float* r = (const float*)d_in[1];
    float* out = (float*)d_out;

    dim3 grid(H, NN, G);                 // 5120 single-group tiles
    gwc_kernel<<<grid, 160>>>(l, r, out);
}